// round 1
// baseline (speedup 1.0000x reference)
#include <cuda_runtime.h>
#include <cstdint>

// ---------------- problem constants ----------------
#define N_MAX 100000
#define E_MAX 1600000
#define IN_DIM 128
#define HID_DIM 128
#define OUT_DIM 64

// ---------------- device scratch ----------------
__device__ int   g_is64;
__device__ int   g_esrc[E_MAX];
__device__ int   g_edst[E_MAX];
__device__ int   g_cnt[N_MAX];
__device__ int   g_rptr[N_MAX + 1];
__device__ int   g_cursor[N_MAX];
__device__ int   g_part[256];
__device__ float g_dinv[N_MAX];
__device__ int   g_csr[E_MAX];
__device__ __align__(16) float g_g1[(size_t)N_MAX * HID_DIM];   // dinv * (x@W1)
__device__ __align__(16) float g_h1[(size_t)N_MAX * HID_DIM];   // relu output of layer 1
__device__ __align__(16) float g_g2[(size_t)N_MAX * OUT_DIM];   // dinv * (h1@W2)

// ---------------- dtype detection & conversion ----------------
__global__ void k_detect(const void* p) {
    const long long* q = (const long long*)p;
    int ok = 1;
    for (int i = 0; i < 8; i++) {
        long long v = q[i];
        if (v < 0 || v >= (long long)N_MAX * 4) ok = 0;
    }
    g_is64 = ok;
}

__global__ void k_convert(const void* p, int E) {
    int e = blockIdx.x * blockDim.x + threadIdx.x;
    if (e >= E) return;
    int s, d;
    if (g_is64) {
        const long long* q = (const long long*)p;
        s = (int)q[e];
        d = (int)q[(size_t)E + e];
    } else {
        const int* q = (const int*)p;
        s = q[e];
        d = q[E + e];
    }
    g_esrc[e] = s;
    g_edst[e] = d;
}

// ---------------- CSR build ----------------
__global__ void k_zero(int n) {
    int i = blockIdx.x * blockDim.x + threadIdx.x;
    if (i < n) g_cnt[i] = 0;
}

__global__ void k_count(int E) {
    int e = blockIdx.x * blockDim.x + threadIdx.x;
    if (e >= E) return;
    atomicAdd(&g_cnt[g_edst[e]], 1);
}

// block-wise inclusive scan (Hillis-Steele, 1024 threads) -> exclusive per element
__global__ void k_scanA(int n) {
    __shared__ int sh[1024];
    int t = threadIdx.x;
    int idx = blockIdx.x * 1024 + t;
    int v = (idx < n) ? g_cnt[idx] : 0;
    sh[t] = v;
    __syncthreads();
#pragma unroll
    for (int off = 1; off < 1024; off <<= 1) {
        int add = (t >= off) ? sh[t - off] : 0;
        __syncthreads();
        sh[t] += add;
        __syncthreads();
    }
    int incl = sh[t];
    if (idx < n) g_rptr[idx] = incl - v;   // exclusive within block
    if (t == 1023) g_part[blockIdx.x] = incl;
}

__global__ void k_scanB(int nb) {
    if (threadIdx.x == 0 && blockIdx.x == 0) {
        int acc = 0;
        for (int i = 0; i < nb; i++) {
            int v = g_part[i];
            g_part[i] = acc;
            acc += v;
        }
    }
}

__global__ void k_scanC(int n, int E) {
    int idx = blockIdx.x * blockDim.x + threadIdx.x;
    if (idx < n) {
        int r = g_rptr[idx] + g_part[idx >> 10];
        g_rptr[idx] = r;
        g_cursor[idx] = r;
        g_dinv[idx] = rsqrtf((float)g_cnt[idx] + 1.0f);
    }
    if (idx == 0) g_rptr[n] = E;
}

__global__ void k_scatter(int E) {
    int e = blockIdx.x * blockDim.x + threadIdx.x;
    if (e >= E) return;
    int d = g_edst[e];
    int pos = atomicAdd(&g_cursor[d], 1);
    g_csr[pos] = g_esrc[e];
}

// ---------------- GEMM: G = dinv .* (X @ W), X is [n,128], W is [128,NC] ----------------
template <int NC>
__global__ __launch_bounds__(256) void k_gemm(
    const float* __restrict__ X, const float* __restrict__ W,
    float* __restrict__ G, int n)
{
    constexpr int BM = 128, BK = 32;
    constexpr int CPT = NC / 16;          // cols per thread (8 or 4)
    __shared__ float xs[BK][BM];
    __shared__ float ws[BK][NC];

    int tid = threadIdx.x;
    int tx = tid & 15;
    int ty = tid >> 4;
    int m0 = ty * 8;
    int c0 = tx * CPT;
    int mbase = blockIdx.x * BM;

    float acc[8][CPT];
#pragma unroll
    for (int i = 0; i < 8; i++)
#pragma unroll
        for (int j = 0; j < CPT; j++) acc[i][j] = 0.0f;

    for (int kc = 0; kc < IN_DIM; kc += BK) {
        // load X tile (transposed into smem): 128 rows x 32 k = 1024 float4
#pragma unroll
        for (int r = 0; r < 4; r++) {
            int li = tid + r * 256;       // 0..1023
            int m = li >> 3;
            int kq = li & 7;
            int row = mbase + m;
            float4 v = make_float4(0.f, 0.f, 0.f, 0.f);
            if (row < n) v = *(const float4*)(X + (size_t)row * IN_DIM + kc + kq * 4);
            xs[kq * 4 + 0][m] = v.x;
            xs[kq * 4 + 1][m] = v.y;
            xs[kq * 4 + 2][m] = v.z;
            xs[kq * 4 + 3][m] = v.w;
        }
        // load W tile: 32 x NC floats
        constexpr int WF4 = BK * NC / 4;
#pragma unroll
        for (int r = 0; r < WF4 / 256; r++) {
            int li = tid + r * 256;
            int k = li / (NC / 4);
            int cq = li % (NC / 4);
            float4 v = *(const float4*)(W + (size_t)(kc + k) * NC + cq * 4);
            *(float4*)&ws[k][cq * 4] = v;
        }
        __syncthreads();

#pragma unroll
        for (int k = 0; k < BK; k++) {
            float a[8];
            *(float4*)&a[0] = *(const float4*)&xs[k][m0];
            *(float4*)&a[4] = *(const float4*)&xs[k][m0 + 4];
            float b[CPT];
#pragma unroll
            for (int j = 0; j < CPT; j += 4)
                *(float4*)&b[j] = *(const float4*)&ws[k][c0 + j];
#pragma unroll
            for (int i = 0; i < 8; i++)
#pragma unroll
                for (int j = 0; j < CPT; j++)
                    acc[i][j] += a[i] * b[j];
        }
        __syncthreads();
    }

#pragma unroll
    for (int i = 0; i < 8; i++) {
        int row = mbase + m0 + i;
        if (row < n) {
            float di = g_dinv[row];
#pragma unroll
            for (int j = 0; j < CPT; j += 4) {
                float4 v;
                v.x = acc[i][j + 0] * di;
                v.y = acc[i][j + 1] * di;
                v.z = acc[i][j + 2] * di;
                v.w = acc[i][j + 3] * di;
                *(float4*)(G + (size_t)row * NC + c0 + j) = v;
            }
        }
    }
}

// ---------------- aggregation: OUT[i] = act(dinv[i]*(sum_{j->i} G[j] + G[i]) + bias) ----------------
template <int NC, bool RELU>
__global__ __launch_bounds__(256) void k_agg(
    const float* __restrict__ G, const float* __restrict__ bias,
    float* __restrict__ OUT, int n)
{
    constexpr int V = NC / 32;            // floats per lane (4 or 2)
    int gw = (blockIdx.x * blockDim.x + threadIdx.x) >> 5;
    int lane = threadIdx.x & 31;
    if (gw >= n) return;

    float acc[V];
    const float* pself = G + (size_t)gw * NC + lane * V;
    if constexpr (V == 4) {
        float4 v = *(const float4*)pself;
        acc[0] = v.x; acc[1] = v.y; acc[2] = v.z; acc[3] = v.w;
    } else {
        float2 v = *(const float2*)pself;
        acc[0] = v.x; acc[1] = v.y;
    }

    int s = g_rptr[gw], e = g_rptr[gw + 1];
    for (int base = s; base < e; base += 32) {
        int idx = base + lane;
        int sj = (idx < e) ? g_csr[idx] : 0;
        int m = e - base; if (m > 32) m = 32;
        int j = 0;
        for (; j + 4 <= m; j += 4) {
            int s0 = __shfl_sync(0xffffffffu, sj, j);
            int s1 = __shfl_sync(0xffffffffu, sj, j + 1);
            int s2 = __shfl_sync(0xffffffffu, sj, j + 2);
            int s3 = __shfl_sync(0xffffffffu, sj, j + 3);
            if constexpr (V == 4) {
                float4 a = *(const float4*)(G + (size_t)s0 * NC + lane * 4);
                float4 b = *(const float4*)(G + (size_t)s1 * NC + lane * 4);
                float4 c = *(const float4*)(G + (size_t)s2 * NC + lane * 4);
                float4 d = *(const float4*)(G + (size_t)s3 * NC + lane * 4);
                acc[0] += a.x + b.x; acc[1] += a.y + b.y;
                acc[2] += a.z + b.z; acc[3] += a.w + b.w;
                acc[0] += c.x + d.x; acc[1] += c.y + d.y;
                acc[2] += c.z + d.z; acc[3] += c.w + d.w;
            } else {
                float2 a = *(const float2*)(G + (size_t)s0 * NC + lane * 2);
                float2 b = *(const float2*)(G + (size_t)s1 * NC + lane * 2);
                float2 c = *(const float2*)(G + (size_t)s2 * NC + lane * 2);
                float2 d = *(const float2*)(G + (size_t)s3 * NC + lane * 2);
                acc[0] += a.x + b.x; acc[1] += a.y + b.y;
                acc[0] += c.x + d.x; acc[1] += c.y + d.y;
            }
        }
        for (; j < m; j++) {
            int s0 = __shfl_sync(0xffffffffu, sj, j);
            const float* p = G + (size_t)s0 * NC + lane * V;
            if constexpr (V == 4) {
                float4 a = *(const float4*)p;
                acc[0] += a.x; acc[1] += a.y; acc[2] += a.z; acc[3] += a.w;
            } else {
                float2 a = *(const float2*)p;
                acc[0] += a.x; acc[1] += a.y;
            }
        }
    }

    float di = g_dinv[gw];
    float bv[V];
    if constexpr (V == 4) {
        float4 b = *(const float4*)(bias + lane * 4);
        bv[0] = b.x; bv[1] = b.y; bv[2] = b.z; bv[3] = b.w;
    } else {
        float2 b = *(const float2*)(bias + lane * 2);
        bv[0] = b.x; bv[1] = b.y;
    }
    float r[V];
#pragma unroll
    for (int v = 0; v < V; v++) {
        r[v] = acc[v] * di + bv[v];
        if (RELU) r[v] = fmaxf(r[v], 0.0f);
    }
    float* po = OUT + (size_t)gw * NC + lane * V;
    if constexpr (V == 4) {
        float4 o; o.x = r[0]; o.y = r[1]; o.z = r[2]; o.w = r[3];
        *(float4*)po = o;
    } else {
        float2 o; o.x = r[0]; o.y = r[1];
        *(float2*)po = o;
    }
}

// ---------------- launch ----------------
extern "C" void kernel_launch(void* const* d_in, const int* in_sizes, int n_in,
                              void* d_out, int out_size)
{
    const float* x  = (const float*)d_in[0];
    const void*  ei = d_in[1];
    const float* W1 = (const float*)d_in[2];
    const float* b1 = (const float*)d_in[3];
    const float* W2 = (const float*)d_in[4];
    const float* b2 = (const float*)d_in[5];
    float* out = (float*)d_out;

    int n = in_sizes[0] / IN_DIM;
    int E = in_sizes[1] / 2;

    float *g1p, *h1p, *g2p;
    cudaGetSymbolAddress((void**)&g1p, g_g1);
    cudaGetSymbolAddress((void**)&h1p, g_h1);
    cudaGetSymbolAddress((void**)&g2p, g_g2);

    int nb1024 = (n + 1023) / 1024;

    // ---- CSR build ----
    k_detect<<<1, 1>>>(ei);
    k_convert<<<(E + 255) / 256, 256>>>(ei, E);
    k_zero<<<(n + 255) / 256, 256>>>(n);
    k_count<<<(E + 255) / 256, 256>>>(E);
    k_scanA<<<nb1024, 1024>>>(n);
    k_scanB<<<1, 32>>>(nb1024);
    k_scanC<<<(n + 255) / 256, 256>>>(n, E);
    k_scatter<<<(E + 255) / 256, 256>>>(E);

    // ---- layer 1 ----
    k_gemm<HID_DIM><<<(n + 127) / 128, 256>>>(x, W1, g1p, n);
    k_agg<HID_DIM, true><<<(n * 32 + 255) / 256, 256>>>(g1p, b1, h1p, n);

    // ---- layer 2 ----
    k_gemm<OUT_DIM><<<(n + 127) / 128, 256>>>(h1p, W2, g2p, n);
    k_agg<OUT_DIM, false><<<(n * 32 + 255) / 256, 256>>>(g2p, b2, out, n);
}

// round 2
// speedup vs baseline: 1.0439x; 1.0439x over previous
#include <cuda_runtime.h>
#include <cstdint>

// ---------------- problem constants ----------------
#define N_MAX 100000
#define E_MAX 1600000
#define IN_DIM 128
#define HID_DIM 128
#define OUT_DIM 64

typedef unsigned long long u64;

// ---------------- device scratch ----------------
__device__ int   g_is64;
__device__ int   g_esrc[E_MAX];
__device__ int   g_edst[E_MAX];
__device__ int   g_cnt[N_MAX];
__device__ int   g_rptr[N_MAX + 1];
__device__ int   g_cursor[N_MAX];
__device__ int   g_part[256];
__device__ float g_dinv[N_MAX];
__device__ int   g_csr[E_MAX];
__device__ __align__(16) float g_g1[(size_t)N_MAX * HID_DIM];   // dinv * (x@W1)
__device__ __align__(16) float g_h1[(size_t)N_MAX * HID_DIM];   // relu output of layer 1
__device__ __align__(16) float g_g2[(size_t)N_MAX * OUT_DIM];   // dinv * (h1@W2)

// ---------------- packed f32x2 helpers ----------------
__device__ __forceinline__ u64 pack_dup(float v) {
    u64 r;
    asm("mov.b64 %0, {%1, %1};" : "=l"(r) : "f"(v));
    return r;
}
__device__ __forceinline__ void fma2(u64& acc, u64 a, u64 b) {
    asm("fma.rn.f32x2 %0, %1, %2, %0;" : "+l"(acc) : "l"(a), "l"(b));
}

// ---------------- dtype detection & conversion ----------------
__global__ void k_detect(const void* p) {
    const long long* q = (const long long*)p;
    int ok = 1;
    for (int i = 0; i < 8; i++) {
        long long v = q[i];
        if (v < 0 || v >= (long long)N_MAX * 4) ok = 0;
    }
    g_is64 = ok;
}

// convert edge dtype AND zero the degree counters in one pass
__global__ void k_convert_zero(const void* p, int E, int n) {
    int e = blockIdx.x * blockDim.x + threadIdx.x;
    if (e < n) g_cnt[e] = 0;
    if (e >= E) return;
    int s, d;
    if (g_is64) {
        const long long* q = (const long long*)p;
        s = (int)q[e];
        d = (int)q[(size_t)E + e];
    } else {
        const int* q = (const int*)p;
        s = q[e];
        d = q[E + e];
    }
    g_esrc[e] = s;
    g_edst[e] = d;
}

// ---------------- CSR build ----------------
__global__ void k_count(int E) {
    int e = blockIdx.x * blockDim.x + threadIdx.x;
    if (e >= E) return;
    atomicAdd(&g_cnt[g_edst[e]], 1);
}

// block-wise inclusive scan (Hillis-Steele, 1024 threads) -> exclusive per element
__global__ void k_scanA(int n) {
    __shared__ int sh[1024];
    int t = threadIdx.x;
    int idx = blockIdx.x * 1024 + t;
    int v = (idx < n) ? g_cnt[idx] : 0;
    sh[t] = v;
    __syncthreads();
#pragma unroll
    for (int off = 1; off < 1024; off <<= 1) {
        int add = (t >= off) ? sh[t - off] : 0;
        __syncthreads();
        sh[t] += add;
        __syncthreads();
    }
    int incl = sh[t];
    if (idx < n) g_rptr[idx] = incl - v;   // exclusive within block
    if (t == 1023) g_part[blockIdx.x] = incl;
}

__global__ void k_scanB(int nb) {
    if (threadIdx.x == 0 && blockIdx.x == 0) {
        int acc = 0;
        for (int i = 0; i < nb; i++) {
            int v = g_part[i];
            g_part[i] = acc;
            acc += v;
        }
    }
}

__global__ void k_scanC(int n, int E) {
    int idx = blockIdx.x * blockDim.x + threadIdx.x;
    if (idx < n) {
        int r = g_rptr[idx] + g_part[idx >> 10];
        g_rptr[idx] = r;
        g_cursor[idx] = r;
        g_dinv[idx] = rsqrtf((float)g_cnt[idx] + 1.0f);
    }
    if (idx == 0) g_rptr[n] = E;
}

__global__ void k_scatter(int E) {
    int e = blockIdx.x * blockDim.x + threadIdx.x;
    if (e >= E) return;
    int d = g_edst[e];
    int pos = atomicAdd(&g_cursor[d], 1);
    g_csr[pos] = g_esrc[e];
}

// ---------------- GEMM: G = dinv .* (X @ W), X is [n,128], W is [128,NC] ----------------
// Packed f32x2 FMA: accumulators paired along M (row pairs), B operand duplicated.
template <int NC>
__global__ __launch_bounds__(256) void k_gemm(
    const float* __restrict__ X, const float* __restrict__ W,
    float* __restrict__ G, int n)
{
    constexpr int BM = 128, BK = 32;
    constexpr int CPT = NC / 16;          // cols per thread (8 or 4)
    __shared__ float xs[BK][BM];
    __shared__ float ws[BK][NC];

    int tid = threadIdx.x;
    int tx = tid & 15;
    int ty = tid >> 4;
    int m0 = ty * 8;
    int c0 = tx * CPT;
    int mbase = blockIdx.x * BM;

    // acc2[p][j]: packed fp32 pair = rows (m0+2p, m0+2p+1), column c0+j
    u64 acc2[4][CPT];
#pragma unroll
    for (int p = 0; p < 4; p++)
#pragma unroll
        for (int j = 0; j < CPT; j++) acc2[p][j] = 0ull;

    for (int kc = 0; kc < IN_DIM; kc += BK) {
        // load X tile (transposed into smem): 128 rows x 32 k = 1024 float4
#pragma unroll
        for (int r = 0; r < 4; r++) {
            int li = tid + r * 256;       // 0..1023
            int m = li >> 3;
            int kq = li & 7;
            int row = mbase + m;
            float4 v = make_float4(0.f, 0.f, 0.f, 0.f);
            if (row < n) v = *(const float4*)(X + (size_t)row * IN_DIM + kc + kq * 4);
            xs[kq * 4 + 0][m] = v.x;
            xs[kq * 4 + 1][m] = v.y;
            xs[kq * 4 + 2][m] = v.z;
            xs[kq * 4 + 3][m] = v.w;
        }
        // load W tile: 32 x NC floats
        constexpr int WF4 = BK * NC / 4;
#pragma unroll
        for (int r = 0; r < WF4 / 256; r++) {
            int li = tid + r * 256;
            int k = li / (NC / 4);
            int cq = li % (NC / 4);
            float4 v = *(const float4*)(W + (size_t)(kc + k) * NC + cq * 4);
            *(float4*)&ws[k][cq * 4] = v;
        }
        __syncthreads();

#pragma unroll
        for (int k = 0; k < BK; k++) {
            // a: 8 consecutive rows -> 4 natural fp32 pairs (no pack cost)
            float4 a01 = *(const float4*)&xs[k][m0];
            float4 a45 = *(const float4*)&xs[k][m0 + 4];
            u64 ap[4];
            ap[0] = *(u64*)&a01.x;
            ap[1] = *(u64*)&a01.z;
            ap[2] = *(u64*)&a45.x;
            ap[3] = *(u64*)&a45.z;
            float b[CPT];
#pragma unroll
            for (int j = 0; j < CPT; j += 4)
                *(float4*)&b[j] = *(const float4*)&ws[k][c0 + j];
#pragma unroll
            for (int j = 0; j < CPT; j++) {
                u64 bd = pack_dup(b[j]);
#pragma unroll
                for (int p = 0; p < 4; p++)
                    fma2(acc2[p][j], ap[p], bd);
            }
        }
        __syncthreads();
    }

    // epilogue: unpack row pairs, scale by dinv, store
#pragma unroll
    for (int p = 0; p < 4; p++) {
#pragma unroll
        for (int half = 0; half < 2; half++) {
            int row = mbase + m0 + 2 * p + half;
            if (row < n) {
                float di = g_dinv[row];
#pragma unroll
                for (int j = 0; j < CPT; j += 4) {
                    float4 v;
                    v.x = ((const float2*)&acc2[p][j + 0])->x * di;
                    v.y = ((const float2*)&acc2[p][j + 1])->x * di;
                    v.z = ((const float2*)&acc2[p][j + 2])->x * di;
                    v.w = ((const float2*)&acc2[p][j + 3])->x * di;
                    if (half) {
                        v.x = ((const float2*)&acc2[p][j + 0])->y * di;
                        v.y = ((const float2*)&acc2[p][j + 1])->y * di;
                        v.z = ((const float2*)&acc2[p][j + 2])->y * di;
                        v.w = ((const float2*)&acc2[p][j + 3])->y * di;
                    }
                    *(float4*)(G + (size_t)row * NC + c0 + j) = v;
                }
            }
        }
    }
}

// ---------------- aggregation: OUT[i] = act(dinv[i]*(sum_{j->i} G[j] + G[i]) + bias) ----------------
template <int NC, bool RELU>
__global__ __launch_bounds__(256) void k_agg(
    const float* __restrict__ G, const float* __restrict__ bias,
    float* __restrict__ OUT, int n)
{
    constexpr int V = NC / 32;            // floats per lane (4 or 2)
    int gw = (blockIdx.x * blockDim.x + threadIdx.x) >> 5;
    int lane = threadIdx.x & 31;
    if (gw >= n) return;

    float acc[V];
    const float* pself = G + (size_t)gw * NC + lane * V;
    if constexpr (V == 4) {
        float4 v = *(const float4*)pself;
        acc[0] = v.x; acc[1] = v.y; acc[2] = v.z; acc[3] = v.w;
    } else {
        float2 v = *(const float2*)pself;
        acc[0] = v.x; acc[1] = v.y;
    }

    int s = g_rptr[gw], e = g_rptr[gw + 1];
    for (int base = s; base < e; base += 32) {
        int idx = base + lane;
        int sj = (idx < e) ? g_csr[idx] : 0;
        int m = e - base; if (m > 32) m = 32;
        int j = 0;
        for (; j + 4 <= m; j += 4) {
            int s0 = __shfl_sync(0xffffffffu, sj, j);
            int s1 = __shfl_sync(0xffffffffu, sj, j + 1);
            int s2 = __shfl_sync(0xffffffffu, sj, j + 2);
            int s3 = __shfl_sync(0xffffffffu, sj, j + 3);
            if constexpr (V == 4) {
                float4 a = *(const float4*)(G + (size_t)s0 * NC + lane * 4);
                float4 b = *(const float4*)(G + (size_t)s1 * NC + lane * 4);
                float4 c = *(const float4*)(G + (size_t)s2 * NC + lane * 4);
                float4 d = *(const float4*)(G + (size_t)s3 * NC + lane * 4);
                acc[0] += a.x + b.x; acc[1] += a.y + b.y;
                acc[2] += a.z + b.z; acc[3] += a.w + b.w;
                acc[0] += c.x + d.x; acc[1] += c.y + d.y;
                acc[2] += c.z + d.z; acc[3] += c.w + d.w;
            } else {
                float2 a = *(const float2*)(G + (size_t)s0 * NC + lane * 2);
                float2 b = *(const float2*)(G + (size_t)s1 * NC + lane * 2);
                float2 c = *(const float2*)(G + (size_t)s2 * NC + lane * 2);
                float2 d = *(const float2*)(G + (size_t)s3 * NC + lane * 2);
                acc[0] += a.x + b.x; acc[1] += a.y + b.y;
                acc[0] += c.x + d.x; acc[1] += c.y + d.y;
            }
        }
        for (; j < m; j++) {
            int s0 = __shfl_sync(0xffffffffu, sj, j);
            const float* p = G + (size_t)s0 * NC + lane * V;
            if constexpr (V == 4) {
                float4 a = *(const float4*)p;
                acc[0] += a.x; acc[1] += a.y; acc[2] += a.z; acc[3] += a.w;
            } else {
                float2 a = *(const float2*)p;
                acc[0] += a.x; acc[1] += a.y;
            }
        }
    }

    float di = g_dinv[gw];
    float bv[V];
    if constexpr (V == 4) {
        float4 b = *(const float4*)(bias + lane * 4);
        bv[0] = b.x; bv[1] = b.y; bv[2] = b.z; bv[3] = b.w;
    } else {
        float2 b = *(const float2*)(bias + lane * 2);
        bv[0] = b.x; bv[1] = b.y;
    }
    float r[V];
#pragma unroll
    for (int v = 0; v < V; v++) {
        r[v] = acc[v] * di + bv[v];
        if (RELU) r[v] = fmaxf(r[v], 0.0f);
    }
    float* po = OUT + (size_t)gw * NC + lane * V;
    if constexpr (V == 4) {
        float4 o; o.x = r[0]; o.y = r[1]; o.z = r[2]; o.w = r[3];
        *(float4*)po = o;
    } else {
        float2 o; o.x = r[0]; o.y = r[1];
        *(float2*)po = o;
    }
}

// ---------------- launch ----------------
extern "C" void kernel_launch(void* const* d_in, const int* in_sizes, int n_in,
                              void* d_out, int out_size)
{
    const float* x  = (const float*)d_in[0];
    const void*  ei = d_in[1];
    const float* W1 = (const float*)d_in[2];
    const float* b1 = (const float*)d_in[3];
    const float* W2 = (const float*)d_in[4];
    const float* b2 = (const float*)d_in[5];
    float* out = (float*)d_out;

    int n = in_sizes[0] / IN_DIM;
    int E = in_sizes[1] / 2;

    float *g1p, *h1p, *g2p;
    cudaGetSymbolAddress((void**)&g1p, g_g1);
    cudaGetSymbolAddress((void**)&h1p, g_h1);
    cudaGetSymbolAddress((void**)&g2p, g_g2);

    int nb1024 = (n + 1023) / 1024;
    int mEn = (E > n) ? E : n;

    // ---- CSR build ----
    k_detect<<<1, 1>>>(ei);
    k_convert_zero<<<(mEn + 255) / 256, 256>>>(ei, E, n);
    k_count<<<(E + 255) / 256, 256>>>(E);
    k_scanA<<<nb1024, 1024>>>(n);
    k_scanB<<<1, 32>>>(nb1024);
    k_scanC<<<(n + 255) / 256, 256>>>(n, E);
    k_scatter<<<(E + 255) / 256, 256>>>(E);

    // ---- layer 1 ----
    k_gemm<HID_DIM><<<(n + 127) / 128, 256>>>(x, W1, g1p, n);
    k_agg<HID_DIM, true><<<(n * 32 + 255) / 256, 256>>>(g1p, b1, h1p, n);

    // ---- layer 2 ----
    k_gemm<OUT_DIM><<<(n + 127) / 128, 256>>>(h1p, W2, g2p, n);
    k_agg<OUT_DIM, false><<<(n * 32 + 255) / 256, 256>>>(g2p, b2, out, n);
}